// round 15
// baseline (speedup 1.0000x reference)
#include <cuda_runtime.h>
#include <cstdint>

#define IN_DIM   16
#define OUT_DIM  32
#define TPB      256
#define WARPS    8
#define RPB      256            // rows per block-tile
#define C15      286331154u     // ceil(2^32/15) (safe-path rounding)
#define FMAGIC   0x4B400000     // 12582912.0f = 1.5 * 2^23

__global__ void __launch_bounds__(TPB, 5)
quant_fused_kernel(const float4* __restrict__ in, float4* __restrict__ out,
                   const float* __restrict__ weight,
                   const float* __restrict__ pInMin,
                   const float* __restrict__ pInMax,
                   int rows, int numTiles) {
    __shared__ __align__(16) uint32_t s_q[WARPS][128];  // 32 rows x 4 packed q chunks
    __shared__ __align__(16) uint32_t s_K[WARPS][128];  // 32 rows x 4 K-words 69*(74-T)<<16
    __shared__ uint4    s_wp[OUT_DIM];
    __shared__ uint4    s_wm[OUT_DIM];
    __shared__ float4   s_bias[OUT_DIM / 4];
    __shared__ int      s_hz;

    const int tid = threadIdx.x;
    const int w = tid >> 5, t = tid & 31;

    const float InMin = *pInMin, InMax = *pInMax;
    const float scale = InMax - InMin;
    const float qa = 15.0f / scale;
    const float qb = -InMin * 15.0f / scale;
    const float scale4 = scale * 0.25f;     // exact (power-of-2 scaling)

    // ---- fused prep (warp 0): pack sign masks, bias, zero-flag ----
    if (tid < 32) {
        int o = tid;
        int anyz = 0, ssum = 0;
        uint32_t wp[4], wm[4];
        #pragma unroll
        for (int c = 0; c < 4; c++) {
            uint32_t p = 0, m = 0;
            #pragma unroll
            for (int j = 0; j < 4; j++) {
                float wv = weight[o * IN_DIM + c * 4 + j];
                int s = (wv > 0.0f) ? 1 : ((wv < 0.0f) ? -1 : 0);
                ssum += s;
                anyz |= (s == 0);
                if (s > 0) p |= 1u << (8 * j);
                if (s < 0) m |= 1u << (8 * j);
            }
            wp[c] = p; wm[c] = m;
        }
        s_wp[o] = make_uint4(wp[0], wp[1], wp[2], wp[3]);
        s_wm[o] = make_uint4(wm[0], wm[1], wm[2], wm[3]);
        ((float*)s_bias)[o] = InMin * (float)ssum;
        unsigned zb = __ballot_sync(0xffffffffu, anyz);
        if (o == 0) s_hz = (zb != 0u) ? 1 : 0;
    }
    __syncthreads();

    const int g  = t >> 3;          // row offset within group-of-4
    const int oq = t & 7;           // output float4 owned by this thread
    const float4 bias = s_bias[oq];

    // float-magic epilogue: term_c = floor(x/15) + floor((x+74-T_c)/15) - 4,
    // so tot4 = 4*(SumLo+SumHi) - 64 and the final-dp4a seed is constant:
    const int seedC = (int)(FMAGIC - 64);
    const float mc = 12582912.0f * scale4;
    const float4 biasM = make_float4(bias.x - mc, bias.y - mc, bias.z - mc, bias.w - mc);

    if (!s_hz) {
        // ================= HOT PATH (no zero-sign weights) =================
        for (int tile = blockIdx.x; tile < numTiles; tile += gridDim.x) {
            int tileRow = tile * RPB + w * 32;

            const float4* ip = in + (size_t)tileRow * 4;
            #pragma unroll
            for (int i = 0; i < 4; i++) {
                int n = i * 32 + t;                    // = rlocal*4 + chunk
                float4 x = make_float4(0.f, 0.f, 0.f, 0.f);
                if (tileRow + (n >> 2) < rows) x = ip[n];
                int e0 = __float2int_rn(fmaf(x.x, qa, qb));
                int e1 = __float2int_rn(fmaf(x.y, qa, qb));
                int e2 = __float2int_rn(fmaf(x.z, qa, qb));
                int e3 = __float2int_rn(fmaf(x.w, qa, qb));
                uint32_t qw = __byte_perm(__byte_perm(e0, e1, 0x0040),
                                          __byte_perm(e2, e3, 0x0040), 0x5410);
                s_q[w][n] = qw;
                unsigned T = __dp4a(qw, 0x01010101u, 14u);   // S_c + 14, <= 74
                // K = (69*(74-T))<<16 = 0x13F20000 - T*0x00450000
                s_K[w][n] = 0x13F20000u - T * 0x00450000u;
            }
            __syncwarp();

            float4* op = out + (size_t)tileRow * 8;
            #pragma unroll 2
            for (int j = 0; j < 8; j++) {
                int r = 4 * j + g;
                uint4 q = ((const uint4*)s_q[w])[r];
                uint4 K = ((const uint4*)s_K[w])[r];
                float4 ov;
                float* ovp = (float*)&ov;
                const float* bp = (const float*)&biasM;
                // weights read from smem each j (conflict-free broadcast LDS.128);
                // frees 16 registers -> 5 CTAs/SM.
                #pragma unroll
                for (int oi = 0; oi < 4; oi++) {
                    uint4 wv = s_wp[oq * 4 + oi];
                    // v = (yP+7)*0x450045 + K; lo lane 69x -> floor(x/15)@bits10-14,
                    // hi lane 69*(x+74-T) -> floor((x+74-T)/15)@bits26-30; fields
                    // accumulate carry-free; bytes 1/3 of acc = Lo<<2 / Hi<<2;
                    // final dp4a = (FMAGIC-64) + 4*(Lo+Hi) = FMAGIC + 4*tot.
                    unsigned acc;
                    acc  = (__dp4a(q.x, wv.x, 7u) * 0x00450045u + K.x) & 0x1C001C00u;
                    acc += (__dp4a(q.y, wv.y, 7u) * 0x00450045u + K.y) & 0x1C001C00u;
                    acc += (__dp4a(q.z, wv.z, 7u) * 0x00450045u + K.z) & 0x1C001C00u;
                    acc += (__dp4a(q.w, wv.w, 7u) * 0x00450045u + K.w) & 0x1C001C00u;
                    ovp[oi] = fmaf(__int_as_float(__dp4a((int)acc, 0x01000100, seedC)),
                                   scale4, bp[oi]);
                }
                if (tileRow + r < rows) op[(size_t)r * 8 + oq] = ov;
            }
            __syncwarp();
        }
    } else {
        // ================= SAFE PATH (some sign(w)==0) =================
        for (int tile = blockIdx.x; tile < numTiles; tile += gridDim.x) {
            int tileRow = tile * RPB + w * 32;

            const float4* ip = in + (size_t)tileRow * 4;
            #pragma unroll
            for (int i = 0; i < 4; i++) {
                int n = i * 32 + t;
                float4 x = make_float4(0.f, 0.f, 0.f, 0.f);
                if (tileRow + (n >> 2) < rows) x = ip[n];
                int e0 = __float2int_rn(fmaf(x.x, qa, qb));
                int e1 = __float2int_rn(fmaf(x.y, qa, qb));
                int e2 = __float2int_rn(fmaf(x.z, qa, qb));
                int e3 = __float2int_rn(fmaf(x.w, qa, qb));
                s_q[w][n] = __byte_perm(__byte_perm(e0, e1, 0x0040),
                                        __byte_perm(e2, e3, 0x0040), 0x5410);
            }
            __syncwarp();

            float4* op = out + (size_t)tileRow * 8;
            #pragma unroll 2
            for (int j = 0; j < 8; j++) {
                int r = 4 * j + g;
                uint4 q = ((const uint4*)s_q[w])[r];
                float4 ov;
                float* ovp = (float*)&ov;
                #pragma unroll
                for (int oi = 0; oi < 4; oi++) {
                    uint4 wp = s_wp[oq * 4 + oi];
                    uint4 wm = s_wm[oq * 4 + oi];
                    unsigned rp0 = __dp4a(q.x, wp.x, 7u), rm0 = __dp4a(q.x, wm.x, 7u);
                    unsigned rp1 = __dp4a(q.y, wp.y, 7u), rm1 = __dp4a(q.y, wm.y, 7u);
                    unsigned rp2 = __dp4a(q.z, wp.z, 7u), rm2 = __dp4a(q.z, wm.z, 7u);
                    unsigned rp3 = __dp4a(q.w, wp.w, 7u), rm3 = __dp4a(q.w, wm.w, 7u);
                    int acc = (int)__umulhi(rp0, C15) - (int)__umulhi(rm0, C15)
                            + (int)__umulhi(rp1, C15) - (int)__umulhi(rm1, C15)
                            + (int)__umulhi(rp2, C15) - (int)__umulhi(rm2, C15)
                            + (int)__umulhi(rp3, C15) - (int)__umulhi(rm3, C15);
                    ovp[oi] = fmaf((float)acc, scale, ((const float*)&bias)[oi]);
                }
                if (tileRow + r < rows) op[(size_t)r * 8 + oq] = ov;
            }
            __syncwarp();
        }
    }
}

extern "C" void kernel_launch(void* const* d_in, const int* in_sizes, int n_in,
                              void* d_out, int out_size) {
    const float* Input  = (const float*)d_in[0];
    const float* weight = (const float*)d_in[1];
    const float* InMin  = (const float*)d_in[2];
    const float* InMax  = (const float*)d_in[3];
    float* out = (float*)d_out;

    int rows = in_sizes[0] / IN_DIM;
    int numTiles = (rows + RPB - 1) / RPB;

    int blocks = 148 * 5;                  // one resident wave at 5 CTAs/SM
    if (blocks > numTiles) blocks = numTiles;

    quant_fused_kernel<<<blocks, TPB>>>((const float4*)Input, (float4*)out,
                                        weight, InMin, InMax, rows, numTiles);
}

// round 16
// speedup vs baseline: 1.3393x; 1.3393x over previous
#include <cuda_runtime.h>
#include <cstdint>

#define IN_DIM   16
#define OUT_DIM  32
#define TPB      256
#define WARPS    8
#define RPB      256            // rows per block-tile
#define C15      286331154u     // ceil(2^32/15) (safe-path rounding)
#define FMAGIC   0x4B400000     // 12582912.0f = 1.5 * 2^23

__device__ unsigned g_ctr  = 0;   // dynamic tile counter (always reset to 0 on exit)
__device__ unsigned g_done = 0;   // block completion counter (ditto)

__global__ void __launch_bounds__(TPB, 4)
quant_fused_kernel(const float4* __restrict__ in, float4* __restrict__ out,
                   const float* __restrict__ weight,
                   const float* __restrict__ pInMin,
                   const float* __restrict__ pInMax,
                   int rows, int numTiles) {
    __shared__ __align__(16) uint32_t s_q[WARPS][128];  // 32 rows x 4 packed q chunks
    __shared__ __align__(16) uint32_t s_K[WARPS][128];  // 32 rows x 4 K-words 69*(74-T)<<16
    __shared__ uint4    s_wp[OUT_DIM];
    __shared__ uint4    s_wm[OUT_DIM];
    __shared__ float4   s_bias[OUT_DIM / 4];
    __shared__ unsigned s_next;
    __shared__ int      s_hz;

    const int tid = threadIdx.x;
    const int w = tid >> 5, t = tid & 31;

    const float InMin = *pInMin, InMax = *pInMax;
    const float scale = InMax - InMin;
    const float qa = 15.0f / scale;
    const float qb = -InMin * 15.0f / scale;
    const float scale4 = scale * 0.25f;     // exact (power-of-2 scaling)

    // ---- fused prep (warp 0): pack sign masks, bias, zero-flag ----
    if (tid < 32) {
        int o = tid;
        int anyz = 0, ssum = 0;
        uint32_t wp[4], wm[4];
        #pragma unroll
        for (int c = 0; c < 4; c++) {
            uint32_t p = 0, m = 0;
            #pragma unroll
            for (int j = 0; j < 4; j++) {
                float wv = weight[o * IN_DIM + c * 4 + j];
                int s = (wv > 0.0f) ? 1 : ((wv < 0.0f) ? -1 : 0);
                ssum += s;
                anyz |= (s == 0);
                if (s > 0) p |= 1u << (8 * j);
                if (s < 0) m |= 1u << (8 * j);
            }
            wp[c] = p; wm[c] = m;
        }
        s_wp[o] = make_uint4(wp[0], wp[1], wp[2], wp[3]);
        s_wm[o] = make_uint4(wm[0], wm[1], wm[2], wm[3]);
        ((float*)s_bias)[o] = InMin * (float)ssum;
        unsigned zb = __ballot_sync(0xffffffffu, anyz);
        if (o == 0) s_hz = (zb != 0u) ? 1 : 0;
    }
    __syncthreads();

    const int g  = t >> 3;          // row offset within group-of-4
    const int oq = t & 7;           // output float4 owned by this thread
    const float4 bias = s_bias[oq];

    // float-magic epilogue: term_c = floor(x/15) + floor((x+74-T_c)/15) - 4,
    // so tot4 = 4*(SumLo+SumHi) - 64 and the final-dp4a seed is constant:
    const int seedC = (int)(FMAGIC - 64);
    const float mc = 12582912.0f * scale4;
    const float4 biasM = make_float4(bias.x - mc, bias.y - mc, bias.z - mc, bias.w - mc);

    const uint4 w0 = s_wp[oq * 4 + 0];
    const uint4 w1 = s_wp[oq * 4 + 1];
    const uint4 w2 = s_wp[oq * 4 + 2];
    const uint4 w3 = s_wp[oq * 4 + 3];

    if (!s_hz) {
        // ======== HOT PATH (no zero-sign weights), dynamic tile stealing ========
        int tile = blockIdx.x;                 // first tile static
        while (tile < numTiles) {
            int tileRow = tile * RPB + w * 32;

            const float4* ip = in + (size_t)tileRow * 4;
            #pragma unroll
            for (int i = 0; i < 4; i++) {
                int n = i * 32 + t;                    // = rlocal*4 + chunk
                float4 x = make_float4(0.f, 0.f, 0.f, 0.f);
                if (tileRow + (n >> 2) < rows) x = ip[n];
                int e0 = __float2int_rn(fmaf(x.x, qa, qb));
                int e1 = __float2int_rn(fmaf(x.y, qa, qb));
                int e2 = __float2int_rn(fmaf(x.z, qa, qb));
                int e3 = __float2int_rn(fmaf(x.w, qa, qb));
                uint32_t qw = __byte_perm(__byte_perm(e0, e1, 0x0040),
                                          __byte_perm(e2, e3, 0x0040), 0x5410);
                s_q[w][n] = qw;
                unsigned T = __dp4a(qw, 0x01010101u, 14u);   // S_c + 14, <= 74
                // K = (69*(74-T))<<16 = 0x13F20000 - T*0x00450000
                s_K[w][n] = 0x13F20000u - T * 0x00450000u;
            }
            __syncwarp();

            // steal next tile early; 318-cyc atomic hides under the main loop
            if (tid == 0) s_next = (unsigned)gridDim.x + atomicAdd(&g_ctr, 1u);

            float4* op = out + (size_t)tileRow * 8;
            #pragma unroll 2
            for (int j = 0; j < 8; j++) {
                int r = 4 * j + g;
                uint4 q = ((const uint4*)s_q[w])[r];
                uint4 K = ((const uint4*)s_K[w])[r];
                float4 ov;
                unsigned acc;
                // v = (yP+7)*0x450045 + K; lo lane 69x -> floor(x/15)@bits10-14,
                // hi lane 69*(x+74-T) -> floor((x+74-T)/15)@bits26-30; carry-free
                // accumulation; bytes 1/3 of acc = Lo<<2 / Hi<<2; final dp4a =
                // (FMAGIC-64) + 4*(Lo+Hi) = FMAGIC + 4*tot (exact in mantissa).
                acc  = (__dp4a(q.x, w0.x, 7u) * 0x00450045u + K.x) & 0x1C001C00u;
                acc += (__dp4a(q.y, w0.y, 7u) * 0x00450045u + K.y) & 0x1C001C00u;
                acc += (__dp4a(q.z, w0.z, 7u) * 0x00450045u + K.z) & 0x1C001C00u;
                acc += (__dp4a(q.w, w0.w, 7u) * 0x00450045u + K.w) & 0x1C001C00u;
                ov.x = fmaf(__int_as_float(__dp4a((int)acc, 0x01000100, seedC)), scale4, biasM.x);
                acc  = (__dp4a(q.x, w1.x, 7u) * 0x00450045u + K.x) & 0x1C001C00u;
                acc += (__dp4a(q.y, w1.y, 7u) * 0x00450045u + K.y) & 0x1C001C00u;
                acc += (__dp4a(q.z, w1.z, 7u) * 0x00450045u + K.z) & 0x1C001C00u;
                acc += (__dp4a(q.w, w1.w, 7u) * 0x00450045u + K.w) & 0x1C001C00u;
                ov.y = fmaf(__int_as_float(__dp4a((int)acc, 0x01000100, seedC)), scale4, biasM.y);
                acc  = (__dp4a(q.x, w2.x, 7u) * 0x00450045u + K.x) & 0x1C001C00u;
                acc += (__dp4a(q.y, w2.y, 7u) * 0x00450045u + K.y) & 0x1C001C00u;
                acc += (__dp4a(q.z, w2.z, 7u) * 0x00450045u + K.z) & 0x1C001C00u;
                acc += (__dp4a(q.w, w2.w, 7u) * 0x00450045u + K.w) & 0x1C001C00u;
                ov.z = fmaf(__int_as_float(__dp4a((int)acc, 0x01000100, seedC)), scale4, biasM.z);
                acc  = (__dp4a(q.x, w3.x, 7u) * 0x00450045u + K.x) & 0x1C001C00u;
                acc += (__dp4a(q.y, w3.y, 7u) * 0x00450045u + K.y) & 0x1C001C00u;
                acc += (__dp4a(q.z, w3.z, 7u) * 0x00450045u + K.z) & 0x1C001C00u;
                acc += (__dp4a(q.w, w3.w, 7u) * 0x00450045u + K.w) & 0x1C001C00u;
                ov.w = fmaf(__int_as_float(__dp4a((int)acc, 0x01000100, seedC)), scale4, biasM.w);
                if (tileRow + r < rows) op[(size_t)r * 8 + oq] = ov;
            }
            __syncthreads();              // s_next valid; all prologue reads done
            tile = (int)s_next;
            __syncthreads();              // everyone read s_next before next write
        }
    } else {
        // ================= SAFE PATH (some sign(w)==0), static =================
        for (int tile = blockIdx.x; tile < numTiles; tile += gridDim.x) {
            int tileRow = tile * RPB + w * 32;

            const float4* ip = in + (size_t)tileRow * 4;
            #pragma unroll
            for (int i = 0; i < 4; i++) {
                int n = i * 32 + t;
                float4 x = make_float4(0.f, 0.f, 0.f, 0.f);
                if (tileRow + (n >> 2) < rows) x = ip[n];
                int e0 = __float2int_rn(fmaf(x.x, qa, qb));
                int e1 = __float2int_rn(fmaf(x.y, qa, qb));
                int e2 = __float2int_rn(fmaf(x.z, qa, qb));
                int e3 = __float2int_rn(fmaf(x.w, qa, qb));
                s_q[w][n] = __byte_perm(__byte_perm(e0, e1, 0x0040),
                                        __byte_perm(e2, e3, 0x0040), 0x5410);
            }
            __syncwarp();

            float4* op = out + (size_t)tileRow * 8;
            #pragma unroll 2
            for (int j = 0; j < 8; j++) {
                int r = 4 * j + g;
                uint4 q = ((const uint4*)s_q[w])[r];
                float4 ov;
                float* ovp = (float*)&ov;
                #pragma unroll
                for (int oi = 0; oi < 4; oi++) {
                    uint4 wp = s_wp[oq * 4 + oi];
                    uint4 wm = s_wm[oq * 4 + oi];
                    unsigned rp0 = __dp4a(q.x, wp.x, 7u), rm0 = __dp4a(q.x, wm.x, 7u);
                    unsigned rp1 = __dp4a(q.y, wp.y, 7u), rm1 = __dp4a(q.y, wm.y, 7u);
                    unsigned rp2 = __dp4a(q.z, wp.z, 7u), rm2 = __dp4a(q.z, wm.z, 7u);
                    unsigned rp3 = __dp4a(q.w, wp.w, 7u), rm3 = __dp4a(q.w, wm.w, 7u);
                    int acc = (int)__umulhi(rp0, C15) - (int)__umulhi(rm0, C15)
                            + (int)__umulhi(rp1, C15) - (int)__umulhi(rm1, C15)
                            + (int)__umulhi(rp2, C15) - (int)__umulhi(rm2, C15)
                            + (int)__umulhi(rp3, C15) - (int)__umulhi(rm3, C15);
                    ovp[oi] = fmaf((float)acc, scale, ((const float*)&bias)[oi]);
                }
                if (tileRow + r < rows) op[(size_t)r * 8 + oq] = ov;
            }
            __syncwarp();
        }
    }

    // ---- deterministic counter reset: last block zeroes both counters ----
    __syncthreads();
    if (tid == 0) {
        if (atomicAdd(&g_done, 1u) == (unsigned)gridDim.x - 1u) {
            atomicExch(&g_ctr, 0u);
            __threadfence();
            atomicExch(&g_done, 0u);
        }
    }
}

extern "C" void kernel_launch(void* const* d_in, const int* in_sizes, int n_in,
                              void* d_out, int out_size) {
    const float* Input  = (const float*)d_in[0];
    const float* weight = (const float*)d_in[1];
    const float* InMin  = (const float*)d_in[2];
    const float* InMax  = (const float*)d_in[3];
    float* out = (float*)d_out;

    int rows = in_sizes[0] / IN_DIM;
    int numTiles = (rows + RPB - 1) / RPB;

    int blocks = 148 * 4;                  // one resident wave at 4 CTAs/SM
    if (blocks > numTiles) blocks = numTiles;

    quant_fused_kernel<<<blocks, TPB>>>((const float4*)Input, (float4*)out,
                                        weight, InMin, InMax, rows, numTiles);
}

// round 17
// speedup vs baseline: 1.3810x; 1.0312x over previous
#include <cuda_runtime.h>
#include <cstdint>

#define IN_DIM   16
#define OUT_DIM  32
#define TPB      256
#define WARPS    8
#define RPB      256            // rows per block-tile
#define C15      286331154u     // ceil(2^32/15) (safe-path rounding)
#define FMAGIC   0x4B400000     // 12582912.0f = 1.5 * 2^23
#define QMUL     0x00450045u
#define QMASK    0x1C001C00u

__device__ unsigned g_ctr  = 0;   // dynamic tile counter (reset to 0 on exit)
__device__ unsigned g_done = 0;   // block completion counter (reset to 0 on exit)

// One output float4 for row (q0..q3 / K0..K3) given 4 weight words.
__device__ __forceinline__ float quant_out(
    uint32_t q0, uint32_t q1, uint32_t q2, uint32_t q3,
    uint32_t K0, uint32_t K1, uint32_t K2, uint32_t K3,
    uint4 wv, int seedC, float scale4, float biasM)
{
    // v = (yP+7)*0x450045 + K; lo lane 69x -> floor(x/15)@bits10-14, hi lane
    // 69*(x+74-T) -> floor((x+74-T)/15)@bits26-30; carry-free accumulation;
    // bytes 1/3 of acc = Lo<<2 / Hi<<2; final dp4a = (FMAGIC-64)+4*(Lo+Hi)
    // = FMAGIC + 4*tot, reinterpreted float = 12582912 + 4*tot (exact).
    unsigned acc;
    acc  = (__dp4a(q0, wv.x, 7u) * QMUL + K0) & QMASK;
    acc += (__dp4a(q1, wv.y, 7u) * QMUL + K1) & QMASK;
    acc += (__dp4a(q2, wv.z, 7u) * QMUL + K2) & QMASK;
    acc += (__dp4a(q3, wv.w, 7u) * QMUL + K3) & QMASK;
    return fmaf(__int_as_float(__dp4a((int)acc, 0x01000100, seedC)), scale4, biasM);
}

__global__ void __launch_bounds__(TPB, 4)
quant_fused_kernel(const float4* __restrict__ in, float4* __restrict__ out,
                   const float* __restrict__ weight,
                   const float* __restrict__ pInMin,
                   const float* __restrict__ pInMax,
                   int rows, int numTiles) {
    // interleaved per-row staging: words 8r..8r+7 = q0,K0,q1,K1,q2,K2,q3,K3
    __shared__ __align__(16) uint32_t s_qk[WARPS][256];
    __shared__ uint4    s_wp[OUT_DIM];
    __shared__ uint4    s_wm[OUT_DIM];
    __shared__ float4   s_bias[OUT_DIM / 4];
    __shared__ unsigned s_next[2];
    __shared__ int      s_hz;

    const int tid = threadIdx.x;
    const int w = tid >> 5, t = tid & 31;

    const float InMin = *pInMin, InMax = *pInMax;
    const float scale = InMax - InMin;
    const float qa = 15.0f / scale;
    const float qb = -InMin * 15.0f / scale;
    const float scale4 = scale * 0.25f;     // exact (power-of-2 scaling)

    // ---- fused prep (warp 0): pack sign masks, bias, zero-flag ----
    if (tid < 32) {
        int o = tid;
        int anyz = 0, ssum = 0;
        uint32_t wp[4], wm[4];
        #pragma unroll
        for (int c = 0; c < 4; c++) {
            uint32_t p = 0, m = 0;
            #pragma unroll
            for (int j = 0; j < 4; j++) {
                float wv = weight[o * IN_DIM + c * 4 + j];
                int s = (wv > 0.0f) ? 1 : ((wv < 0.0f) ? -1 : 0);
                ssum += s;
                anyz |= (s == 0);
                if (s > 0) p |= 1u << (8 * j);
                if (s < 0) m |= 1u << (8 * j);
            }
            wp[c] = p; wm[c] = m;
        }
        s_wp[o] = make_uint4(wp[0], wp[1], wp[2], wp[3]);
        s_wm[o] = make_uint4(wm[0], wm[1], wm[2], wm[3]);
        ((float*)s_bias)[o] = InMin * (float)ssum;
        unsigned zb = __ballot_sync(0xffffffffu, anyz);
        if (o == 0) s_hz = (zb != 0u) ? 1 : 0;
    }
    __syncthreads();

    const int g  = t >> 3;          // row offset within group-of-4
    const int oq = t & 7;           // output float4 owned by this thread
    const float4 bias = s_bias[oq];

    // term_c = floor(x/15) + floor((x+74-T_c)/15) - 4 -> constant final seed:
    const int seedC = (int)(FMAGIC - 64);
    const float mc = 12582912.0f * scale4;
    const float4 biasM = make_float4(bias.x - mc, bias.y - mc, bias.z - mc, bias.w - mc);

    const uint4 w0 = s_wp[oq * 4 + 0];
    const uint4 w1 = s_wp[oq * 4 + 1];
    const uint4 w2 = s_wp[oq * 4 + 2];
    const uint4 w3 = s_wp[oq * 4 + 3];

    if (!s_hz) {
        // ======== HOT PATH (no zero-sign weights), dynamic tile stealing ========
        int tile = blockIdx.x;                 // first tile static
        int ph = 0;
        while (tile < numTiles) {
            int tileRow = tile * RPB + w * 32;
            bool full = (tileRow + 32 <= rows);

            const float4* ip = in + (size_t)tileRow * 4;
            if (full) {
                #pragma unroll
                for (int i = 0; i < 4; i++) {
                    int n = i * 32 + t;                // = rlocal*4 + chunk
                    float4 x = ip[n];
                    int e0 = __float2int_rn(fmaf(x.x, qa, qb));
                    int e1 = __float2int_rn(fmaf(x.y, qa, qb));
                    int e2 = __float2int_rn(fmaf(x.z, qa, qb));
                    int e3 = __float2int_rn(fmaf(x.w, qa, qb));
                    uint32_t qw = __byte_perm(__byte_perm(e0, e1, 0x0040),
                                              __byte_perm(e2, e3, 0x0040), 0x5410);
                    unsigned T = __dp4a(qw, 0x01010101u, 14u);      // S_c+14 <= 74
                    uint32_t Kv = 0x13F20000u - T * 0x00450000u;    // (69*(74-T))<<16
                    *(uint2*)&s_qk[w][2 * n] = make_uint2(qw, Kv);
                }
            } else {
                #pragma unroll
                for (int i = 0; i < 4; i++) {
                    int n = i * 32 + t;
                    float4 x = make_float4(0.f, 0.f, 0.f, 0.f);
                    if (tileRow + (n >> 2) < rows) x = ip[n];
                    int e0 = __float2int_rn(fmaf(x.x, qa, qb));
                    int e1 = __float2int_rn(fmaf(x.y, qa, qb));
                    int e2 = __float2int_rn(fmaf(x.z, qa, qb));
                    int e3 = __float2int_rn(fmaf(x.w, qa, qb));
                    uint32_t qw = __byte_perm(__byte_perm(e0, e1, 0x0040),
                                              __byte_perm(e2, e3, 0x0040), 0x5410);
                    unsigned T = __dp4a(qw, 0x01010101u, 14u);
                    uint32_t Kv = 0x13F20000u - T * 0x00450000u;
                    *(uint2*)&s_qk[w][2 * n] = make_uint2(qw, Kv);
                }
            }
            __syncwarp();

            // steal next tile early; atomic latency hides under the main loop.
            // ping-pong slot: written slot is read after THIS tile's barrier;
            // the other slot's readers are separated by an intervening barrier.
            if (tid == 0) s_next[ph ^ 1] = (unsigned)gridDim.x + atomicAdd(&g_ctr, 1u);

            const uint4* pqk = (const uint4*)&s_qk[w][8 * g];   // +128B per j
            float4* po = out + (size_t)tileRow * 8 + g * 8 + oq;
            if (full) {
                #pragma unroll 2
                for (int j = 0; j < 8; j++) {
                    uint4 A = pqk[j * 8];        // q0,K0,q1,K1
                    uint4 B = pqk[j * 8 + 1];    // q2,K2,q3,K3
                    float4 ov;
                    ov.x = quant_out(A.x, A.z, B.x, B.z, A.y, A.w, B.y, B.w,
                                     w0, seedC, scale4, biasM.x);
                    ov.y = quant_out(A.x, A.z, B.x, B.z, A.y, A.w, B.y, B.w,
                                     w1, seedC, scale4, biasM.y);
                    ov.z = quant_out(A.x, A.z, B.x, B.z, A.y, A.w, B.y, B.w,
                                     w2, seedC, scale4, biasM.z);
                    ov.w = quant_out(A.x, A.z, B.x, B.z, A.y, A.w, B.y, B.w,
                                     w3, seedC, scale4, biasM.w);
                    po[j * 32] = ov;
                }
            } else {
                #pragma unroll 2
                for (int j = 0; j < 8; j++) {
                    int r = 4 * j + g;
                    uint4 A = pqk[j * 8];
                    uint4 B = pqk[j * 8 + 1];
                    float4 ov;
                    ov.x = quant_out(A.x, A.z, B.x, B.z, A.y, A.w, B.y, B.w,
                                     w0, seedC, scale4, biasM.x);
                    ov.y = quant_out(A.x, A.z, B.x, B.z, A.y, A.w, B.y, B.w,
                                     w1, seedC, scale4, biasM.y);
                    ov.z = quant_out(A.x, A.z, B.x, B.z, A.y, A.w, B.y, B.w,
                                     w2, seedC, scale4, biasM.z);
                    ov.w = quant_out(A.x, A.z, B.x, B.z, A.y, A.w, B.y, B.w,
                                     w3, seedC, scale4, biasM.w);
                    if (tileRow + r < rows) po[j * 32] = ov;
                }
            }
            __syncthreads();              // s_next[ph^1] valid; staging reads done
            tile = (int)s_next[ph ^ 1];
            ph ^= 1;
        }
    } else {
        // ================= SAFE PATH (some sign(w)==0), static =================
        for (int tile = blockIdx.x; tile < numTiles; tile += gridDim.x) {
            int tileRow = tile * RPB + w * 32;

            const float4* ip = in + (size_t)tileRow * 4;
            #pragma unroll
            for (int i = 0; i < 4; i++) {
                int n = i * 32 + t;
                float4 x = make_float4(0.f, 0.f, 0.f, 0.f);
                if (tileRow + (n >> 2) < rows) x = ip[n];
                int e0 = __float2int_rn(fmaf(x.x, qa, qb));
                int e1 = __float2int_rn(fmaf(x.y, qa, qb));
                int e2 = __float2int_rn(fmaf(x.z, qa, qb));
                int e3 = __float2int_rn(fmaf(x.w, qa, qb));
                uint32_t qw = __byte_perm(__byte_perm(e0, e1, 0x0040),
                                          __byte_perm(e2, e3, 0x0040), 0x5410);
                *(uint2*)&s_qk[w][2 * n] = make_uint2(qw, 0u);
            }
            __syncwarp();

            const uint4* pqk = (const uint4*)&s_qk[w][8 * g];
            float4* op = out + (size_t)tileRow * 8;
            #pragma unroll 2
            for (int j = 0; j < 8; j++) {
                int r = 4 * j + g;
                uint4 A = pqk[j * 8];
                uint4 B = pqk[j * 8 + 1];
                uint4 q = make_uint4(A.x, A.z, B.x, B.z);
                float4 ov;
                float* ovp = (float*)&ov;
                #pragma unroll
                for (int oi = 0; oi < 4; oi++) {
                    uint4 wp = s_wp[oq * 4 + oi];
                    uint4 wm = s_wm[oq * 4 + oi];
                    unsigned rp0 = __dp4a(q.x, wp.x, 7u), rm0 = __dp4a(q.x, wm.x, 7u);
                    unsigned rp1 = __dp4a(q.y, wp.y, 7u), rm1 = __dp4a(q.y, wm.y, 7u);
                    unsigned rp2 = __dp4a(q.z, wp.z, 7u), rm2 = __dp4a(q.z, wm.z, 7u);
                    unsigned rp3 = __dp4a(q.w, wp.w, 7u), rm3 = __dp4a(q.w, wm.w, 7u);
                    int acc = (int)__umulhi(rp0, C15) - (int)__umulhi(rm0, C15)
                            + (int)__umulhi(rp1, C15) - (int)__umulhi(rm1, C15)
                            + (int)__umulhi(rp2, C15) - (int)__umulhi(rm2, C15)
                            + (int)__umulhi(rp3, C15) - (int)__umulhi(rm3, C15);
                    ovp[oi] = fmaf((float)acc, scale, ((const float*)&bias)[oi]);
                }
                if (tileRow + r < rows) op[(size_t)r * 8 + oq] = ov;
            }
            __syncwarp();
        }
    }

    // ---- deterministic counter reset: last block zeroes both counters ----
    __syncthreads();
    if (tid == 0) {
        if (atomicAdd(&g_done, 1u) == (unsigned)gridDim.x - 1u) {
            atomicExch(&g_ctr, 0u);
            __threadfence();
            atomicExch(&g_done, 0u);
        }
    }
}

extern "C" void kernel_launch(void* const* d_in, const int* in_sizes, int n_in,
                              void* d_out, int out_size) {
    const float* Input  = (const float*)d_in[0];
    const float* weight = (const float*)d_in[1];
    const float* InMin  = (const float*)d_in[2];
    const float* InMax  = (const float*)d_in[3];
    float* out = (float*)d_out;

    int rows = in_sizes[0] / IN_DIM;
    int numTiles = (rows + RPB - 1) / RPB;

    int blocks = 148 * 4;                  // one resident wave at 4 CTAs/SM
    if (blocks > numTiles) blocks = numTiles;

    quant_fused_kernel<<<blocks, TPB>>>((const float4*)Input, (float4*)out,
                                        weight, InMin, InMax, rows, numTiles);
}